// round 7
// baseline (speedup 1.0000x reference)
#include <cuda_runtime.h>
#include <math.h>

#define NN 10000
#define NE 320000
#define F0 512
#define F1 256
#define F2 64
#define NB 79            // ceil(10000/128)

// ---- scratch (no cudaMalloc allowed) ----
__device__ int   g_cnt[NN];
__device__ int   g_ptr[NN + 1];
__device__ int   g_cur[NN];
__device__ int   g_csr[NE];
__device__ float g_dis[NN];
__device__ __align__(16) float g_XW[NN * F1];   // X @ W1   (unscaled)
__device__ __align__(16) float g_H1[NN * F1];   // layer-1 output
__device__ __align__(16) float g_HW[NN * F2];   // H1 @ W2  (unscaled)
__device__ __align__(16) float g_Z [NN * F2];   // layer-2 output

// ---- tf32 / cp.async helpers ----
__device__ __forceinline__ unsigned f2tf(float f) {
    unsigned u; asm("cvt.rna.tf32.f32 %0, %1;" : "=r"(u) : "f"(f)); return u;
}
__device__ __forceinline__ void mma_tf32(float& d0, float& d1, float& d2, float& d3,
                                         unsigned a0, unsigned a1, unsigned a2, unsigned a3,
                                         unsigned b0, unsigned b1) {
    asm volatile("mma.sync.aligned.m16n8k8.row.col.f32.tf32.tf32.f32 "
                 "{%0,%1,%2,%3}, {%4,%5,%6,%7}, {%8,%9}, {%0,%1,%2,%3};"
                 : "+f"(d0), "+f"(d1), "+f"(d2), "+f"(d3)
                 : "r"(a0), "r"(a1), "r"(a2), "r"(a3), "r"(b0), "r"(b1));
}
__device__ __forceinline__ void cpa16(float* dst_smem, const float* src, bool pred) {
    unsigned sa = (unsigned)__cvta_generic_to_shared(dst_smem);
    int sz = pred ? 16 : 0;
    asm volatile("cp.async.cg.shared.global [%0], [%1], 16, %2;" :: "r"(sa), "l"(src), "r"(sz));
}
#define CP_COMMIT() asm volatile("cp.async.commit_group;")
#define CP_WAIT1()  asm volatile("cp.async.wait_group 1;")

__device__ __forceinline__ float fsig(float x) {
    return __fdividef(1.0f, 1.0f + __expf(-x));   // MUFU EX2 + MUFU RCP path
}

// ================= CSR build =================
__global__ void k_count(const int* __restrict__ dst, int E) {
    int i = blockIdx.x * 256 + threadIdx.x;
    if (i < E) atomicAdd(&g_cnt[dst[i]], 1);
}
__global__ void __launch_bounds__(1024) k_scan() {
    __shared__ int wsum[32];
    __shared__ int carry_s;
    int t = threadIdx.x, lane = t & 31, w = t >> 5;
    if (t == 0) carry_s = 0;
    __syncthreads();
    for (int base = 0; base < NN; base += 1024) {
        int i = base + t;
        int v = (i < NN) ? g_cnt[i] : 0;
        int s = v;
#pragma unroll
        for (int off = 1; off < 32; off <<= 1) {
            int x = __shfl_up_sync(0xFFFFFFFFu, s, off);
            if (lane >= off) s += x;
        }
        if (lane == 31) wsum[w] = s;
        __syncthreads();
        if (w == 0) {
            int y = wsum[lane];
#pragma unroll
            for (int off = 1; off < 32; off <<= 1) {
                int x = __shfl_up_sync(0xFFFFFFFFu, y, off);
                if (lane >= off) y += x;
            }
            wsum[lane] = y;
        }
        __syncthreads();
        int incl = s + (w > 0 ? wsum[w - 1] : 0) + carry_s;
        if (i < NN) {
            g_ptr[i] = incl - v;
            g_cur[i] = incl - v;
            g_dis[i] = rsqrtf((float)(v + 1));
        }
        __syncthreads();
        if (t == 0) carry_s += wsum[31];
        __syncthreads();
    }
    if (t == 0) g_ptr[NN] = carry_s;
}
__global__ void k_scatter(const int* __restrict__ src, const int* __restrict__ dst, int E) {
    int i = blockIdx.x * 256 + threadIdx.x;
    if (i < E) {
        int pos = atomicAdd(&g_cur[dst[i]], 1);
        g_csr[pos] = src[i];
    }
}

// ================= tf32 GEMM, cp.async double-buffered (pure C = A @ B) ==========
#define GEMM_SMEM ((2*128*36 + 2*32*72) * 4)
template<int K, int NC, int MODE>
__global__ void __launch_bounds__(256) k_gemm(const float* __restrict__ Aarg,
                                              const float* __restrict__ B, int M)
{
    const float* A = (MODE == 0) ? Aarg : (const float*)g_H1;
    float*       C = (MODE == 0) ? g_XW : g_HW;

    extern __shared__ float gsm[];
    float* Asm = gsm;                    // [2][128][36]
    float* Bsm = gsm + 2 * 128 * 36;     // [2][32][72]
#define ASF(s, r, c) Asm[(s) * (128 * 36) + (r) * 36 + (c)]
#define BSF(s, r, c) Bsm[(s) * (32 * 72) + (r) * 72 + (c)]

    int t = threadIdx.x, lane = t & 31, wid = t >> 5;
    int wm = (wid & 3) * 32, wn = (wid >> 2) * 32;
    int g = lane >> 2, q = lane & 3;
    int bm0 = blockIdx.y * 128, bn0 = blockIdx.x * 64;

    float acc[2][4][4];
#pragma unroll
    for (int i = 0; i < 2; ++i)
#pragma unroll
        for (int j = 0; j < 4; ++j)
#pragma unroll
            for (int x = 0; x < 4; ++x) acc[i][j][x] = 0.f;

    const int KT = K / 32;

    auto load_tile = [&](int kt, int s) {
#pragma unroll
        for (int it = 0; it < 4; ++it) {
            int idx = t + it * 256;
            int row = idx >> 3, c4 = (idx & 7) << 2;
            int rg = bm0 + row;
            bool ok = rg < M;
            const float* sp = &A[(size_t)(ok ? rg : 0) * K + kt * 32 + c4];
            cpa16(&ASF(s, row, c4), sp, ok);
        }
#pragma unroll
        for (int it = 0; it < 2; ++it) {
            int idx = t + it * 256;
            int row = idx >> 4, c4 = (idx & 15) << 2;
            cpa16(&BSF(s, row, c4), &B[(size_t)(kt * 32 + row) * NC + bn0 + c4], true);
        }
    };

    load_tile(0, 0);
    CP_COMMIT();

    for (int kt = 0; kt < KT; ++kt) {
        int cb = kt & 1;
        if (kt + 1 < KT) load_tile(kt + 1, cb ^ 1);
        CP_COMMIT();
        CP_WAIT1();
        __syncthreads();

#pragma unroll
        for (int ks = 0; ks < 4; ++ks) {
            int kk = ks * 8;
            unsigned bf[4][2];
#pragma unroll
            for (int j = 0; j < 4; ++j) {
                bf[j][0] = f2tf(BSF(cb, kk + q,     wn + j * 8 + g));
                bf[j][1] = f2tf(BSF(cb, kk + q + 4, wn + j * 8 + g));
            }
#pragma unroll
            for (int i = 0; i < 2; ++i) {
                int r = wm + i * 16 + g;
                unsigned a0 = f2tf(ASF(cb, r,     kk + q));
                unsigned a1 = f2tf(ASF(cb, r + 8, kk + q));
                unsigned a2 = f2tf(ASF(cb, r,     kk + q + 4));
                unsigned a3 = f2tf(ASF(cb, r + 8, kk + q + 4));
#pragma unroll
                for (int j = 0; j < 4; ++j)
                    mma_tf32(acc[i][j][0], acc[i][j][1], acc[i][j][2], acc[i][j][3],
                             a0, a1, a2, a3, bf[j][0], bf[j][1]);
            }
        }
        __syncthreads();
    }

#pragma unroll
    for (int i = 0; i < 2; ++i) {
        int r0 = bm0 + wm + i * 16 + g;
#pragma unroll
        for (int j = 0; j < 4; ++j) {
            int c = bn0 + wn + j * 8 + q * 2;
            if (r0 < M)     *(float2*)&C[(size_t)r0 * NC + c]       = make_float2(acc[i][j][0], acc[i][j][1]);
            if (r0 + 8 < M) *(float2*)&C[(size_t)(r0 + 8) * NC + c] = make_float2(acc[i][j][2], acc[i][j][3]);
        }
    }
#undef ASF
#undef BSF
}

// ================= CSR aggregation (no atomics; dis applied here) =================
// H[d] = dis[d] * ( dis[d]*C[d] + sum_s dis[s]*C[s] ) + bias
// F=256: warp per node; 4-way neighbor unroll (8 float4 loads in flight).
__global__ void __launch_bounds__(256) k_agg256(const float* __restrict__ bias)
{
    int gt = blockIdx.x * 256 + threadIdx.x;
    int d = gt >> 5, lane = gt & 31;
    if (d >= NN) return;
    float dd = g_dis[d];
    const float4* selfp = (const float4*)&g_XW[(size_t)d * 256];
    float4 s0 = selfp[lane], s1 = selfp[lane + 32];
    float4 a0 = make_float4(s0.x * dd, s0.y * dd, s0.z * dd, s0.w * dd);
    float4 a1 = make_float4(s1.x * dd, s1.y * dd, s1.z * dd, s1.w * dd);
    int e = g_ptr[d], e1 = g_ptr[d + 1];
    for (; e + 3 < e1; e += 4) {
        int   n[4]; float ds[4]; const float4* p[4];
#pragma unroll
        for (int u = 0; u < 4; ++u) {
            n[u] = g_csr[e + u];
            ds[u] = g_dis[n[u]];
            p[u] = (const float4*)&g_XW[(size_t)n[u] * 256];
        }
        float4 v0[4], v1[4];
#pragma unroll
        for (int u = 0; u < 4; ++u) { v0[u] = p[u][lane]; v1[u] = p[u][lane + 32]; }
#pragma unroll
        for (int u = 0; u < 4; ++u) {
            a0.x += v0[u].x * ds[u]; a0.y += v0[u].y * ds[u];
            a0.z += v0[u].z * ds[u]; a0.w += v0[u].w * ds[u];
            a1.x += v1[u].x * ds[u]; a1.y += v1[u].y * ds[u];
            a1.z += v1[u].z * ds[u]; a1.w += v1[u].w * ds[u];
        }
    }
    for (; e < e1; ++e) {
        int n0 = g_csr[e];
        float ds0 = g_dis[n0];
        const float4* p0 = (const float4*)&g_XW[(size_t)n0 * 256];
        float4 v00 = p0[lane], v01 = p0[lane + 32];
        a0.x += v00.x * ds0; a0.y += v00.y * ds0; a0.z += v00.z * ds0; a0.w += v00.w * ds0;
        a1.x += v01.x * ds0; a1.y += v01.y * ds0; a1.z += v01.z * ds0; a1.w += v01.w * ds0;
    }
    float4 b0 = ((const float4*)bias)[lane], b1 = ((const float4*)bias)[lane + 32];
    float4* hp = (float4*)&g_H1[(size_t)d * 256];
    hp[lane]      = make_float4(a0.x * dd + b0.x, a0.y * dd + b0.y, a0.z * dd + b0.z, a0.w * dd + b0.w);
    hp[lane + 32] = make_float4(a1.x * dd + b1.x, a1.y * dd + b1.y, a1.z * dd + b1.z, a1.w * dd + b1.w);
}
// F=64: warp per node, lane holds float2; 4-way unroll.
__global__ void __launch_bounds__(256) k_agg64(const float* __restrict__ bias)
{
    int gt = blockIdx.x * 256 + threadIdx.x;
    int d = gt >> 5, lane = gt & 31;
    if (d >= NN) return;
    float dd = g_dis[d];
    float2 sv = *(const float2*)&g_HW[(size_t)d * 64 + lane * 2];
    float2 acc = make_float2(sv.x * dd, sv.y * dd);
    int e = g_ptr[d], e1 = g_ptr[d + 1];
    for (; e + 3 < e1; e += 4) {
        int n[4]; float ds[4]; float2 v[4];
#pragma unroll
        for (int u = 0; u < 4; ++u) { n[u] = g_csr[e + u]; ds[u] = g_dis[n[u]]; }
#pragma unroll
        for (int u = 0; u < 4; ++u) v[u] = *(const float2*)&g_HW[(size_t)n[u] * 64 + lane * 2];
#pragma unroll
        for (int u = 0; u < 4; ++u) { acc.x += v[u].x * ds[u]; acc.y += v[u].y * ds[u]; }
    }
    for (; e < e1; ++e) {
        int n0 = g_csr[e];
        float ds0 = g_dis[n0];
        float2 v = *(const float2*)&g_HW[(size_t)n0 * 64 + lane * 2];
        acc.x += v.x * ds0; acc.y += v.y * ds0;
    }
    float2 b = *(const float2*)&bias[lane * 2];
    *(float2*)&g_Z[(size_t)d * 64 + lane * 2] = make_float2(acc.x * dd + b.x, acc.y * dd + b.y);
}

// ================= decoder: Y = sigmoid(Z Z^T), tf32, triangular grid =================
// Both output halves routed through smem -> STG.128 rows.
#define DEC_SMEM (128*68*4 + 64*136*4)   // 69632 B; T[128][132] (67584 B) aliases it
#define TS 132
__global__ void __launch_bounds__(256) k_decode(float* __restrict__ Y, int M)
{
    int k = blockIdx.x;
    int bi = (int)((2.0f * NB + 1.0f - sqrtf((2.0f * NB + 1.0f) * (2.0f * NB + 1.0f) - 8.0f * k)) * 0.5f);
    if (bi < 0) bi = 0;
    while (bi * NB - bi * (bi - 1) / 2 > k) --bi;
    while ((bi + 1) * NB - (bi + 1) * bi / 2 <= k) ++bi;
    int bj = bi + (k - (bi * NB - bi * (bi - 1) / 2));

    extern __shared__ unsigned char sraw[];
    unsigned (*As)[68]  = (unsigned(*)[68])sraw;                  // [128][68]
    unsigned (*Bs)[136] = (unsigned(*)[136])(sraw + 128*68*4);    // [64][136]
    float* T = (float*)sraw;                                      // [128][TS] store phases

    int t = threadIdx.x, lane = t & 31, wid = t >> 5;
    int wm = (wid & 3) * 32, wn = (wid >> 2) * 64;
    int g = lane >> 2, q = lane & 3;
    int r0b = bi * 128, c0b = bj * 128;

#pragma unroll
    for (int it = 0; it < 8; ++it) {
        int idx = t + it * 256;
        int row = idx >> 4, c4 = (idx & 15) << 2;
        float4 v = make_float4(0.f, 0.f, 0.f, 0.f);
        if (r0b + row < M) v = *(const float4*)&g_Z[(r0b + row) * 64 + c4];
        *(uint4*)&As[row][c4] = make_uint4(f2tf(v.x), f2tf(v.y), f2tf(v.z), f2tf(v.w));
    }
#pragma unroll
    for (int it = 0; it < 8; ++it) {
        int idx = t + it * 256;
        int col = idx & 127, c4 = (idx >> 7) << 2;
        float4 v = make_float4(0.f, 0.f, 0.f, 0.f);
        if (c0b + col < M) v = *(const float4*)&g_Z[(c0b + col) * 64 + c4];
        Bs[c4 + 0][col] = f2tf(v.x); Bs[c4 + 1][col] = f2tf(v.y);
        Bs[c4 + 2][col] = f2tf(v.z); Bs[c4 + 3][col] = f2tf(v.w);
    }
    __syncthreads();

    float acc[2][8][4];
#pragma unroll
    for (int i = 0; i < 2; ++i)
#pragma unroll
        for (int j = 0; j < 8; ++j)
#pragma unroll
            for (int x = 0; x < 4; ++x) acc[i][j][x] = 0.f;

#pragma unroll
    for (int ks = 0; ks < 8; ++ks) {
        int kk = ks * 8;
        unsigned bf[8][2];
#pragma unroll
        for (int j = 0; j < 8; ++j) {
            bf[j][0] = Bs[kk + q][wn + j * 8 + g];
            bf[j][1] = Bs[kk + q + 4][wn + j * 8 + g];
        }
#pragma unroll
        for (int i = 0; i < 2; ++i) {
            int r = wm + i * 16 + g;
            unsigned a0 = As[r][kk + q],     a1 = As[r + 8][kk + q];
            unsigned a2 = As[r][kk + q + 4], a3 = As[r + 8][kk + q + 4];
#pragma unroll
            for (int j = 0; j < 8; ++j)
                mma_tf32(acc[i][j][0], acc[i][j][1], acc[i][j][2], acc[i][j][3],
                         a0, a1, a2, a3, bf[j][0], bf[j][1]);
        }
    }

    // sigmoid via MUFU (EX2 + approx-rcp)
#pragma unroll
    for (int i = 0; i < 2; ++i)
#pragma unroll
        for (int j = 0; j < 8; ++j)
#pragma unroll
            for (int x = 0; x < 4; ++x)
                acc[i][j][x] = fsig(acc[i][j][x]);

    // phase A: normal half via smem row-major -> STG.128 rows of Y
    __syncthreads();            // all MMA smem reads done; T may alias As/Bs
#pragma unroll
    for (int i = 0; i < 2; ++i) {
        int rr = wm + i * 16 + g;
#pragma unroll
        for (int j = 0; j < 8; ++j) {
            int cc = wn + j * 8 + q * 2;
            *(float2*)&T[rr * TS + cc]       = make_float2(acc[i][j][0], acc[i][j][1]);
            *(float2*)&T[(rr + 8) * TS + cc] = make_float2(acc[i][j][2], acc[i][j][3]);
        }
    }
    __syncthreads();
#pragma unroll
    for (int it = 0; it < 16; ++it) {
        int idx = t + it * 256;
        int row = idx >> 5, c4 = (idx & 31) << 2;
        int rg = r0b + row;
        if (rg < M) {
            float4 v = *(const float4*)&T[row * TS + c4];
            int cg = c0b + c4;
            if (cg + 3 < M) {
                *(float4*)&Y[(size_t)rg * M + cg] = v;
            } else {
                float vv[4] = {v.x, v.y, v.z, v.w};
                for (int j = 0; j < 4; ++j)
                    if (cg + j < M) Y[(size_t)rg * M + cg + j] = vv[j];
            }
        }
    }

    // phase B: mirrored half via smem transpose -> STG.128 rows of Y
    if (bi != bj) {
        __syncthreads();
#pragma unroll
        for (int i = 0; i < 2; ++i) {
#pragma unroll
            for (int j = 0; j < 8; ++j) {
                int cc = wn + j * 8 + q * 2;
                int rr = wm + i * 16 + g;
                T[cc * TS + rr]           = acc[i][j][0];
                T[(cc + 1) * TS + rr]     = acc[i][j][1];
                T[cc * TS + rr + 8]       = acc[i][j][2];
                T[(cc + 1) * TS + rr + 8] = acc[i][j][3];
            }
        }
        __syncthreads();
#pragma unroll
        for (int it = 0; it < 16; ++it) {
            int idx = t + it * 256;
            int cc = idx >> 5, rc = (idx & 31) << 2;
            int crow = c0b + cc;
            if (crow < M) {
                float4 v = *(const float4*)&T[cc * TS + rc];
                if (r0b + rc + 3 < M) {
                    *(float4*)&Y[(size_t)crow * M + r0b + rc] = v;
                } else {
                    float vv[4] = {v.x, v.y, v.z, v.w};
                    for (int j = 0; j < 4; ++j)
                        if (r0b + rc + j < M) Y[(size_t)crow * M + r0b + rc + j] = vv[j];
                }
            }
        }
    }
}

// ================= launch =================
extern "C" void kernel_launch(void* const* d_in, const int* in_sizes, int n_in,
                              void* d_out, int out_size)
{
    const float* X  = (const float*)d_in[0];
    const int*   ei = (const int*)  d_in[1];
    const float* W1 = (const float*)d_in[2];
    const float* b1 = (const float*)d_in[3];
    const float* W2 = (const float*)d_in[4];
    const float* b2 = (const float*)d_in[5];
    float* Y = (float*)d_out;

    int E = in_sizes[1] / 2;
    if (E > NE) E = NE;
    const int* src = ei;
    const int* dst = ei + E;

    static bool init_done = false;
    static cudaStream_t s2;
    static cudaEvent_t evA, evB;
    static void* p_cnt;
    if (!init_done) {
        cudaFuncSetAttribute(k_decode, cudaFuncAttributeMaxDynamicSharedMemorySize, DEC_SMEM);
        cudaFuncSetAttribute(k_gemm<F0, F1, 0>, cudaFuncAttributeMaxDynamicSharedMemorySize, GEMM_SMEM);
        cudaFuncSetAttribute(k_gemm<F1, F2, 1>, cudaFuncAttributeMaxDynamicSharedMemorySize, GEMM_SMEM);
        cudaStreamCreateWithFlags(&s2, cudaStreamNonBlocking);
        cudaEventCreateWithFlags(&evA, cudaEventDisableTiming);
        cudaEventCreateWithFlags(&evB, cudaEventDisableTiming);
        cudaGetSymbolAddress(&p_cnt, g_cnt);
        init_done = true;
    }

    // fork: gemm1 (X,W1 only) on s2; CSR build on stream 0
    cudaEventRecord(evA, 0);
    cudaStreamWaitEvent(s2, evA, 0);

    dim3 g1(F1 / 64, (NN + 127) / 128);
    k_gemm<F0, F1, 0><<<g1, 256, GEMM_SMEM, s2>>>(X, W1, NN);
    cudaEventRecord(evB, s2);

    cudaMemsetAsync(p_cnt, 0, NN * sizeof(int), 0);
    k_count  <<<(E + 255) / 256, 256>>>(dst, E);
    k_scan   <<<1, 1024>>>();
    k_scatter<<<(E + 255) / 256, 256>>>(src, dst, E);

    // join: agg256 needs gemm1 (s2) + CSR/dis (stream 0)
    cudaStreamWaitEvent(0, evB, 0);

    k_agg256<<<(NN * 32 + 255) / 256, 256>>>(b1);

    dim3 g2(F2 / 64, (NN + 127) / 128);
    k_gemm<F1, F2, 1><<<g2, 256, GEMM_SMEM>>>(nullptr, W2, NN);
    k_agg64<<<(NN * 32 + 255) / 256, 256>>>(b2);

    k_decode<<<NB * (NB + 1) / 2, 256, DEC_SMEM>>>(Y, NN);
}

// round 8
// speedup vs baseline: 1.2546x; 1.2546x over previous
#include <cuda_runtime.h>
#include <math.h>

#define NN 10000
#define NE 320000
#define F0 512
#define F1 256
#define F2 64
#define NB 79            // ceil(10000/128)

// ---- scratch (no cudaMalloc allowed) ----
__device__ int   g_cnt[NN];
__device__ int   g_ptr[NN + 1];
__device__ int   g_cur[NN];
__device__ int   g_csr[NE];
__device__ float g_dis[NN];
__device__ __align__(16) float g_XW[NN * F1];   // X @ W1   (unscaled)
__device__ __align__(16) float g_H1[NN * F1];   // layer-1 output
__device__ __align__(16) float g_HW[NN * F2];   // H1 @ W2  (unscaled)
__device__ __align__(16) float g_Z [NN * F2];   // layer-2 output

// ---- tf32 / cp.async helpers ----
// NOTE: we feed RAW fp32 bits to mma.tf32 (HW truncates mantissa). Error is
// ~1 tf32 ulp worse than cvt.rna — far inside the 1e-3 budget.
__device__ __forceinline__ unsigned bits(float f) { return __float_as_uint(f); }
__device__ __forceinline__ void mma_tf32(float& d0, float& d1, float& d2, float& d3,
                                         unsigned a0, unsigned a1, unsigned a2, unsigned a3,
                                         unsigned b0, unsigned b1) {
    asm volatile("mma.sync.aligned.m16n8k8.row.col.f32.tf32.tf32.f32 "
                 "{%0,%1,%2,%3}, {%4,%5,%6,%7}, {%8,%9}, {%0,%1,%2,%3};"
                 : "+f"(d0), "+f"(d1), "+f"(d2), "+f"(d3)
                 : "r"(a0), "r"(a1), "r"(a2), "r"(a3), "r"(b0), "r"(b1));
}
__device__ __forceinline__ void cpa16(float* dst_smem, const float* src, bool pred) {
    unsigned sa = (unsigned)__cvta_generic_to_shared(dst_smem);
    int sz = pred ? 16 : 0;
    asm volatile("cp.async.cg.shared.global [%0], [%1], 16, %2;" :: "r"(sa), "l"(src), "r"(sz));
}
#define CP_COMMIT() asm volatile("cp.async.commit_group;")
#define CP_WAIT1()  asm volatile("cp.async.wait_group 1;")

__device__ __forceinline__ float fsig(float x) {
    return __fdividef(1.0f, 1.0f + __expf(-x));   // MUFU EX2 + MUFU RCP path
}

// ================= CSR build =================
__global__ void k_count(const int* __restrict__ dst, int E) {
    int i = blockIdx.x * 256 + threadIdx.x;
    if (i < E) atomicAdd(&g_cnt[dst[i]], 1);
}
__global__ void __launch_bounds__(1024) k_scan() {
    __shared__ int wsum[32];
    __shared__ int carry_s;
    int t = threadIdx.x, lane = t & 31, w = t >> 5;
    if (t == 0) carry_s = 0;
    __syncthreads();
    for (int base = 0; base < NN; base += 1024) {
        int i = base + t;
        int v = (i < NN) ? g_cnt[i] : 0;
        int s = v;
#pragma unroll
        for (int off = 1; off < 32; off <<= 1) {
            int x = __shfl_up_sync(0xFFFFFFFFu, s, off);
            if (lane >= off) s += x;
        }
        if (lane == 31) wsum[w] = s;
        __syncthreads();
        if (w == 0) {
            int y = wsum[lane];
#pragma unroll
            for (int off = 1; off < 32; off <<= 1) {
                int x = __shfl_up_sync(0xFFFFFFFFu, y, off);
                if (lane >= off) y += x;
            }
            wsum[lane] = y;
        }
        __syncthreads();
        int incl = s + (w > 0 ? wsum[w - 1] : 0) + carry_s;
        if (i < NN) {
            g_ptr[i] = incl - v;
            g_cur[i] = incl - v;
            g_dis[i] = rsqrtf((float)(v + 1));
        }
        __syncthreads();
        if (t == 0) carry_s += wsum[31];
        __syncthreads();
    }
    if (t == 0) g_ptr[NN] = carry_s;
}
__global__ void k_scatter(const int* __restrict__ src, const int* __restrict__ dst, int E) {
    int i = blockIdx.x * 256 + threadIdx.x;
    if (i < E) {
        int pos = atomicAdd(&g_cur[dst[i]], 1);
        g_csr[pos] = src[i];
    }
}

// ================= tf32 GEMM, cp.async double-buffered (pure C = A @ B) ==========
#define GEMM_SMEM ((2*128*36 + 2*32*72) * 4)
template<int K, int NC, int MODE>
__global__ void __launch_bounds__(256) k_gemm(const float* __restrict__ Aarg,
                                              const float* __restrict__ B, int M)
{
    const float* A = (MODE == 0) ? Aarg : (const float*)g_H1;
    float*       C = (MODE == 0) ? g_XW : g_HW;

    extern __shared__ float gsm[];
    float* Asm = gsm;                    // [2][128][36]
    float* Bsm = gsm + 2 * 128 * 36;     // [2][32][72]
#define ASF(s, r, c) Asm[(s) * (128 * 36) + (r) * 36 + (c)]
#define BSF(s, r, c) Bsm[(s) * (32 * 72) + (r) * 72 + (c)]

    int t = threadIdx.x, lane = t & 31, wid = t >> 5;
    int wm = (wid & 3) * 32, wn = (wid >> 2) * 32;
    int g = lane >> 2, q = lane & 3;
    int bm0 = blockIdx.y * 128, bn0 = blockIdx.x * 64;

    float acc[2][4][4];
#pragma unroll
    for (int i = 0; i < 2; ++i)
#pragma unroll
        for (int j = 0; j < 4; ++j)
#pragma unroll
            for (int x = 0; x < 4; ++x) acc[i][j][x] = 0.f;

    const int KT = K / 32;

    auto load_tile = [&](int kt, int s) {
#pragma unroll
        for (int it = 0; it < 4; ++it) {
            int idx = t + it * 256;
            int row = idx >> 3, c4 = (idx & 7) << 2;
            int rg = bm0 + row;
            bool ok = rg < M;
            const float* sp = &A[(size_t)(ok ? rg : 0) * K + kt * 32 + c4];
            cpa16(&ASF(s, row, c4), sp, ok);
        }
#pragma unroll
        for (int it = 0; it < 2; ++it) {
            int idx = t + it * 256;
            int row = idx >> 4, c4 = (idx & 15) << 2;
            cpa16(&BSF(s, row, c4), &B[(size_t)(kt * 32 + row) * NC + bn0 + c4], true);
        }
    };

    load_tile(0, 0);
    CP_COMMIT();

    for (int kt = 0; kt < KT; ++kt) {
        int cb = kt & 1;
        if (kt + 1 < KT) load_tile(kt + 1, cb ^ 1);
        CP_COMMIT();
        CP_WAIT1();
        __syncthreads();

#pragma unroll
        for (int ks = 0; ks < 4; ++ks) {
            int kk = ks * 8;
            unsigned bf[4][2];
#pragma unroll
            for (int j = 0; j < 4; ++j) {
                bf[j][0] = bits(BSF(cb, kk + q,     wn + j * 8 + g));
                bf[j][1] = bits(BSF(cb, kk + q + 4, wn + j * 8 + g));
            }
#pragma unroll
            for (int i = 0; i < 2; ++i) {
                int r = wm + i * 16 + g;
                unsigned a0 = bits(ASF(cb, r,     kk + q));
                unsigned a1 = bits(ASF(cb, r + 8, kk + q));
                unsigned a2 = bits(ASF(cb, r,     kk + q + 4));
                unsigned a3 = bits(ASF(cb, r + 8, kk + q + 4));
#pragma unroll
                for (int j = 0; j < 4; ++j)
                    mma_tf32(acc[i][j][0], acc[i][j][1], acc[i][j][2], acc[i][j][3],
                             a0, a1, a2, a3, bf[j][0], bf[j][1]);
            }
        }
        __syncthreads();
    }

#pragma unroll
    for (int i = 0; i < 2; ++i) {
        int r0 = bm0 + wm + i * 16 + g;
#pragma unroll
        for (int j = 0; j < 4; ++j) {
            int c = bn0 + wn + j * 8 + q * 2;
            if (r0 < M)     *(float2*)&C[(size_t)r0 * NC + c]       = make_float2(acc[i][j][0], acc[i][j][1]);
            if (r0 + 8 < M) *(float2*)&C[(size_t)(r0 + 8) * NC + c] = make_float2(acc[i][j][2], acc[i][j][3]);
        }
    }
#undef ASF
#undef BSF
}

// ================= CSR aggregation (no atomics; dis applied here) =================
// H[d] = dis[d] * ( dis[d]*C[d] + sum_s dis[s]*C[s] ) + bias
__global__ void __launch_bounds__(256) k_agg256(const float* __restrict__ bias)
{
    int gt = blockIdx.x * 256 + threadIdx.x;
    int d = gt >> 5, lane = gt & 31;
    if (d >= NN) return;
    float dd = g_dis[d];
    const float4* selfp = (const float4*)&g_XW[(size_t)d * 256];
    float4 s0 = selfp[lane], s1 = selfp[lane + 32];
    float4 a0 = make_float4(s0.x * dd, s0.y * dd, s0.z * dd, s0.w * dd);
    float4 a1 = make_float4(s1.x * dd, s1.y * dd, s1.z * dd, s1.w * dd);
    int e = g_ptr[d], e1 = g_ptr[d + 1];
    for (; e + 3 < e1; e += 4) {
        int   n[4]; float ds[4]; const float4* p[4];
#pragma unroll
        for (int u = 0; u < 4; ++u) {
            n[u] = g_csr[e + u];
            ds[u] = g_dis[n[u]];
            p[u] = (const float4*)&g_XW[(size_t)n[u] * 256];
        }
        float4 v0[4], v1[4];
#pragma unroll
        for (int u = 0; u < 4; ++u) { v0[u] = p[u][lane]; v1[u] = p[u][lane + 32]; }
#pragma unroll
        for (int u = 0; u < 4; ++u) {
            a0.x += v0[u].x * ds[u]; a0.y += v0[u].y * ds[u];
            a0.z += v0[u].z * ds[u]; a0.w += v0[u].w * ds[u];
            a1.x += v1[u].x * ds[u]; a1.y += v1[u].y * ds[u];
            a1.z += v1[u].z * ds[u]; a1.w += v1[u].w * ds[u];
        }
    }
    for (; e < e1; ++e) {
        int n0 = g_csr[e];
        float ds0 = g_dis[n0];
        const float4* p0 = (const float4*)&g_XW[(size_t)n0 * 256];
        float4 v00 = p0[lane], v01 = p0[lane + 32];
        a0.x += v00.x * ds0; a0.y += v00.y * ds0; a0.z += v00.z * ds0; a0.w += v00.w * ds0;
        a1.x += v01.x * ds0; a1.y += v01.y * ds0; a1.z += v01.z * ds0; a1.w += v01.w * ds0;
    }
    float4 b0 = ((const float4*)bias)[lane], b1 = ((const float4*)bias)[lane + 32];
    float4* hp = (float4*)&g_H1[(size_t)d * 256];
    hp[lane]      = make_float4(a0.x * dd + b0.x, a0.y * dd + b0.y, a0.z * dd + b0.z, a0.w * dd + b0.w);
    hp[lane + 32] = make_float4(a1.x * dd + b1.x, a1.y * dd + b1.y, a1.z * dd + b1.z, a1.w * dd + b1.w);
}
__global__ void __launch_bounds__(256) k_agg64(const float* __restrict__ bias)
{
    int gt = blockIdx.x * 256 + threadIdx.x;
    int d = gt >> 5, lane = gt & 31;
    if (d >= NN) return;
    float dd = g_dis[d];
    float2 sv = *(const float2*)&g_HW[(size_t)d * 64 + lane * 2];
    float2 acc = make_float2(sv.x * dd, sv.y * dd);
    int e = g_ptr[d], e1 = g_ptr[d + 1];
    for (; e + 3 < e1; e += 4) {
        int n[4]; float ds[4]; float2 v[4];
#pragma unroll
        for (int u = 0; u < 4; ++u) { n[u] = g_csr[e + u]; ds[u] = g_dis[n[u]]; }
#pragma unroll
        for (int u = 0; u < 4; ++u) v[u] = *(const float2*)&g_HW[(size_t)n[u] * 64 + lane * 2];
#pragma unroll
        for (int u = 0; u < 4; ++u) { acc.x += v[u].x * ds[u]; acc.y += v[u].y * ds[u]; }
    }
    for (; e < e1; ++e) {
        int n0 = g_csr[e];
        float ds0 = g_dis[n0];
        float2 v = *(const float2*)&g_HW[(size_t)n0 * 64 + lane * 2];
        acc.x += v.x * ds0; acc.y += v.y * ds0;
    }
    float2 b = *(const float2*)&bias[lane * 2];
    *(float2*)&g_Z[(size_t)d * 64 + lane * 2] = make_float2(acc.x * dd + b.x, acc.y * dd + b.y);
}

// ================= decoder: Y = sigmoid(Z Z^T) =================
// 512 threads, 16 warps (4m x 4n), warp tile 32x32 -> acc=32 regs/thread.
// Direct float2 stores for the normal half; smem transpose for the mirror.
#define DEC_SMEM (128*68*4 + 64*136*4)   // 69632 B; T[128][132] aliases it
#define TS 132
__global__ void __launch_bounds__(512) k_decode(float* __restrict__ Y, int M)
{
    int k = blockIdx.x;
    int bi = (int)((2.0f * NB + 1.0f - sqrtf((2.0f * NB + 1.0f) * (2.0f * NB + 1.0f) - 8.0f * k)) * 0.5f);
    if (bi < 0) bi = 0;
    while (bi * NB - bi * (bi - 1) / 2 > k) --bi;
    while ((bi + 1) * NB - (bi + 1) * bi / 2 <= k) ++bi;
    int bj = bi + (k - (bi * NB - bi * (bi - 1) / 2));

    extern __shared__ unsigned char sraw[];
    unsigned (*As)[68]  = (unsigned(*)[68])sraw;                  // [128][68]
    unsigned (*Bs)[136] = (unsigned(*)[136])(sraw + 128*68*4);    // [64][136]
    float* T = (float*)sraw;                                      // [128][TS] mirror phase

    int t = threadIdx.x, lane = t & 31, wid = t >> 5;
    int wm = (wid & 3) * 32, wn = (wid >> 2) * 32;   // 4m x 4n warps
    int g = lane >> 2, q = lane & 3;
    int r0b = bi * 128, c0b = bj * 128;

    // A tile: raw fp32 bits (tf32 = truncated f32 in HW)
#pragma unroll
    for (int it = 0; it < 4; ++it) {
        int idx = t + it * 512;           // 2048: 128 rows x 16 float4
        int row = idx >> 4, c4 = (idx & 15) << 2;
        uint4 v = make_uint4(0u, 0u, 0u, 0u);
        if (r0b + row < M) v = *(const uint4*)&g_Z[(r0b + row) * 64 + c4];
        *(uint4*)&As[row][c4] = v;
    }
    // B tile transposed: Bs[k][col] = Z[c0b+col][k]
#pragma unroll
    for (int it = 0; it < 4; ++it) {
        int idx = t + it * 512;
        int col = idx & 127, c4 = (idx >> 7) << 2;
        uint4 v = make_uint4(0u, 0u, 0u, 0u);
        if (c0b + col < M) v = *(const uint4*)&g_Z[(c0b + col) * 64 + c4];
        Bs[c4 + 0][col] = v.x; Bs[c4 + 1][col] = v.y;
        Bs[c4 + 2][col] = v.z; Bs[c4 + 3][col] = v.w;
    }
    __syncthreads();

    float acc[2][4][4];
#pragma unroll
    for (int i = 0; i < 2; ++i)
#pragma unroll
        for (int j = 0; j < 4; ++j)
#pragma unroll
            for (int x = 0; x < 4; ++x) acc[i][j][x] = 0.f;

#pragma unroll
    for (int ks = 0; ks < 8; ++ks) {
        int kk = ks * 8;
        unsigned bf[4][2];
#pragma unroll
        for (int j = 0; j < 4; ++j) {
            bf[j][0] = Bs[kk + q][wn + j * 8 + g];
            bf[j][1] = Bs[kk + q + 4][wn + j * 8 + g];
        }
#pragma unroll
        for (int i = 0; i < 2; ++i) {
            int r = wm + i * 16 + g;
            unsigned a0 = As[r][kk + q],     a1 = As[r + 8][kk + q];
            unsigned a2 = As[r][kk + q + 4], a3 = As[r + 8][kk + q + 4];
#pragma unroll
            for (int j = 0; j < 4; ++j)
                mma_tf32(acc[i][j][0], acc[i][j][1], acc[i][j][2], acc[i][j][3],
                         a0, a1, a2, a3, bf[j][0], bf[j][1]);
        }
    }

    // sigmoid (MUFU)
#pragma unroll
    for (int i = 0; i < 2; ++i)
#pragma unroll
        for (int j = 0; j < 4; ++j)
#pragma unroll
            for (int x = 0; x < 4; ++x)
                acc[i][j][x] = fsig(acc[i][j][x]);

    // normal half: direct float2 stores (L2 assembles full lines)
#pragma unroll
    for (int i = 0; i < 2; ++i) {
        int r = r0b + wm + i * 16 + g;
#pragma unroll
        for (int j = 0; j < 4; ++j) {
            int c = c0b + wn + j * 8 + q * 2;
            if (c < M) {
                if (r < M)     *(float2*)&Y[(size_t)r * M + c]       = make_float2(acc[i][j][0], acc[i][j][1]);
                if (r + 8 < M) *(float2*)&Y[(size_t)(r + 8) * M + c] = make_float2(acc[i][j][2], acc[i][j][3]);
            }
        }
    }

    // mirror half via smem transpose -> STG.128 rows
    if (bi != bj) {
        __syncthreads();                 // all MMA smem reads done; T aliases As/Bs
#pragma unroll
        for (int i = 0; i < 2; ++i) {
#pragma unroll
            for (int j = 0; j < 4; ++j) {
                int cc = wn + j * 8 + q * 2;
                int rr = wm + i * 16 + g;
                T[cc * TS + rr]           = acc[i][j][0];
                T[(cc + 1) * TS + rr]     = acc[i][j][1];
                T[cc * TS + rr + 8]       = acc[i][j][2];
                T[(cc + 1) * TS + rr + 8] = acc[i][j][3];
            }
        }
        __syncthreads();
#pragma unroll
        for (int it = 0; it < 8; ++it) {
            int idx = t + it * 512;      // 4096 = 128 cols x 32 float4
            int cc = idx >> 5, rc = (idx & 31) << 2;
            int crow = c0b + cc;
            if (crow < M) {
                float4 v = *(const float4*)&T[cc * TS + rc];
                if (r0b + rc + 3 < M) {
                    *(float4*)&Y[(size_t)crow * M + r0b + rc] = v;
                } else {
                    float vv[4] = {v.x, v.y, v.z, v.w};
                    for (int j = 0; j < 4; ++j)
                        if (r0b + rc + j < M) Y[(size_t)crow * M + r0b + rc + j] = vv[j];
                }
            }
        }
    }
}

// ================= launch =================
extern "C" void kernel_launch(void* const* d_in, const int* in_sizes, int n_in,
                              void* d_out, int out_size)
{
    const float* X  = (const float*)d_in[0];
    const int*   ei = (const int*)  d_in[1];
    const float* W1 = (const float*)d_in[2];
    const float* b1 = (const float*)d_in[3];
    const float* W2 = (const float*)d_in[4];
    const float* b2 = (const float*)d_in[5];
    float* Y = (float*)d_out;

    int E = in_sizes[1] / 2;
    if (E > NE) E = NE;
    const int* src = ei;
    const int* dst = ei + E;

    static bool init_done = false;
    static cudaStream_t s2;
    static cudaEvent_t evA, evB;
    static void* p_cnt;
    if (!init_done) {
        cudaFuncSetAttribute(k_decode, cudaFuncAttributeMaxDynamicSharedMemorySize, DEC_SMEM);
        cudaFuncSetAttribute(k_gemm<F0, F1, 0>, cudaFuncAttributeMaxDynamicSharedMemorySize, GEMM_SMEM);
        cudaFuncSetAttribute(k_gemm<F1, F2, 1>, cudaFuncAttributeMaxDynamicSharedMemorySize, GEMM_SMEM);
        cudaStreamCreateWithFlags(&s2, cudaStreamNonBlocking);
        cudaEventCreateWithFlags(&evA, cudaEventDisableTiming);
        cudaEventCreateWithFlags(&evB, cudaEventDisableTiming);
        cudaGetSymbolAddress(&p_cnt, g_cnt);
        init_done = true;
    }

    // fork: gemm1 (X,W1 only) on s2; CSR build on stream 0
    cudaEventRecord(evA, 0);
    cudaStreamWaitEvent(s2, evA, 0);

    dim3 g1(F1 / 64, (NN + 127) / 128);
    k_gemm<F0, F1, 0><<<g1, 256, GEMM_SMEM, s2>>>(X, W1, NN);
    cudaEventRecord(evB, s2);

    cudaMemsetAsync(p_cnt, 0, NN * sizeof(int), 0);
    k_count  <<<(E + 255) / 256, 256>>>(dst, E);
    k_scan   <<<1, 1024>>>();
    k_scatter<<<(E + 255) / 256, 256>>>(src, dst, E);

    // join: agg256 needs gemm1 (s2) + CSR/dis (stream 0)
    cudaStreamWaitEvent(0, evB, 0);

    k_agg256<<<(NN * 32 + 255) / 256, 256>>>(b1);

    dim3 g2(F2 / 64, (NN + 127) / 128);
    k_gemm<F1, F2, 1><<<g2, 256, GEMM_SMEM>>>(nullptr, W2, NN);
    k_agg64<<<(NN * 32 + 255) / 256, 256>>>(b2);

    k_decode<<<NB * (NB + 1) / 2, 512, DEC_SMEM>>>(Y, NN);
}

// round 9
// speedup vs baseline: 1.3361x; 1.0650x over previous
#include <cuda_runtime.h>
#include <math.h>

#define NN 10000
#define NE 320000
#define F0 512
#define F2 64
#define NB 79            // ceil(10000/128)

// ---- scratch (no cudaMalloc allowed) ----
__device__ int   g_cnt[NN];
__device__ int   g_ptr[NN + 1];
__device__ int   g_cur[NN];
__device__ int   g_csr[NE];
__device__ float g_dis[NN];
__device__ float g_u[NN];                         // (L·1)[d]
__device__ __align__(16) float g_W12[F0 * F2];    // W1 @ W2 (fp32)
__device__ __align__(16) float g_c[F2];           // b1^T W2
__device__ __align__(16) float g_C1[NN * F2];     // X @ W12
__device__ __align__(16) float g_T1[NN * F2];     // L @ C1
__device__ __align__(16) float g_Z [NN * F2];     // L @ T1 + u c^T + b2

// ---- tf32 (raw-bit) / cp.async helpers ----
__device__ __forceinline__ unsigned bits(float f) { return __float_as_uint(f); }
__device__ __forceinline__ void mma_tf32(float& d0, float& d1, float& d2, float& d3,
                                         unsigned a0, unsigned a1, unsigned a2, unsigned a3,
                                         unsigned b0, unsigned b1) {
    asm volatile("mma.sync.aligned.m16n8k8.row.col.f32.tf32.tf32.f32 "
                 "{%0,%1,%2,%3}, {%4,%5,%6,%7}, {%8,%9}, {%0,%1,%2,%3};"
                 : "+f"(d0), "+f"(d1), "+f"(d2), "+f"(d3)
                 : "r"(a0), "r"(a1), "r"(a2), "r"(a3), "r"(b0), "r"(b1));
}
__device__ __forceinline__ void cpa16(float* dst_smem, const float* src, bool pred) {
    unsigned sa = (unsigned)__cvta_generic_to_shared(dst_smem);
    int sz = pred ? 16 : 0;
    asm volatile("cp.async.cg.shared.global [%0], [%1], 16, %2;" :: "r"(sa), "l"(src), "r"(sz));
}
#define CP_COMMIT() asm volatile("cp.async.commit_group;")
#define CP_WAIT1()  asm volatile("cp.async.wait_group 1;")

__device__ __forceinline__ float fsig(float x) {
    return __fdividef(1.0f, 1.0f + __expf(-x));
}

// ================= CSR build =================
__global__ void k_count(const int* __restrict__ dst, int E) {
    int i = blockIdx.x * 256 + threadIdx.x;
    if (i < E) atomicAdd(&g_cnt[dst[i]], 1);
}
__global__ void __launch_bounds__(1024) k_scan() {
    __shared__ int wsum[32];
    __shared__ int carry_s;
    int t = threadIdx.x, lane = t & 31, w = t >> 5;
    if (t == 0) carry_s = 0;
    __syncthreads();
    for (int base = 0; base < NN; base += 1024) {
        int i = base + t;
        int v = (i < NN) ? g_cnt[i] : 0;
        int s = v;
#pragma unroll
        for (int off = 1; off < 32; off <<= 1) {
            int x = __shfl_up_sync(0xFFFFFFFFu, s, off);
            if (lane >= off) s += x;
        }
        if (lane == 31) wsum[w] = s;
        __syncthreads();
        if (w == 0) {
            int y = wsum[lane];
#pragma unroll
            for (int off = 1; off < 32; off <<= 1) {
                int x = __shfl_up_sync(0xFFFFFFFFu, y, off);
                if (lane >= off) y += x;
            }
            wsum[lane] = y;
        }
        __syncthreads();
        int incl = s + (w > 0 ? wsum[w - 1] : 0) + carry_s;
        if (i < NN) {
            g_ptr[i] = incl - v;
            g_cur[i] = incl - v;
            g_dis[i] = rsqrtf((float)(v + 1));
        }
        __syncthreads();
        if (t == 0) carry_s += wsum[31];
        __syncthreads();
    }
    if (t == 0) g_ptr[NN] = carry_s;
}
__global__ void k_scatter(const int* __restrict__ src, const int* __restrict__ dst, int E) {
    int i = blockIdx.x * 256 + threadIdx.x;
    if (i < E) {
        int pos = atomicAdd(&g_cur[dst[i]], 1);
        g_csr[pos] = src[i];
    }
}

// ================= W12 = W1 @ W2 (fp32), c = b1^T W2 =================
// 513 blocks x 64 threads. Block k<512: W12 row k. Block 512: c.
__global__ void __launch_bounds__(64) k_w12(const float* __restrict__ W1,
                                            const float* __restrict__ W2,
                                            const float* __restrict__ b1)
{
    int n = threadIdx.x;
    int k = blockIdx.x;
    const float* a = (k < F0) ? &W1[k * 256] : b1;
    float acc = 0.f;
#pragma unroll 4
    for (int j = 0; j < 256; ++j) acc = fmaf(a[j], W2[j * F2 + n], acc);
    if (k < F0) g_W12[k * F2 + n] = acc;
    else        g_c[n] = acc;
}

// ================= tf32 GEMM: C = A @ B.  BM=128, BN=64, BK=32 =================
#define GEMM_SMEM ((2*128*36 + 2*32*72) * 4)
template<int K, int NC>
__global__ void __launch_bounds__(256) k_gemm(const float* __restrict__ A,
                                              const float* __restrict__ B,
                                              float* __restrict__ C, int M)
{
    extern __shared__ float gsm[];
    float* Asm = gsm;                    // [2][128][36]
    float* Bsm = gsm + 2 * 128 * 36;     // [2][32][72]
#define ASF(s, r, c) Asm[(s) * (128 * 36) + (r) * 36 + (c)]
#define BSF(s, r, c) Bsm[(s) * (32 * 72) + (r) * 72 + (c)]

    int t = threadIdx.x, lane = t & 31, wid = t >> 5;
    int wm = (wid & 3) * 32, wn = (wid >> 2) * 32;
    int g = lane >> 2, q = lane & 3;
    int bm0 = blockIdx.y * 128, bn0 = blockIdx.x * 64;

    float acc[2][4][4];
#pragma unroll
    for (int i = 0; i < 2; ++i)
#pragma unroll
        for (int j = 0; j < 4; ++j)
#pragma unroll
            for (int x = 0; x < 4; ++x) acc[i][j][x] = 0.f;

    const int KT = K / 32;

    auto load_tile = [&](int kt, int s) {
#pragma unroll
        for (int it = 0; it < 4; ++it) {
            int idx = t + it * 256;
            int row = idx >> 3, c4 = (idx & 7) << 2;
            int rg = bm0 + row;
            bool ok = rg < M;
            const float* sp = &A[(size_t)(ok ? rg : 0) * K + kt * 32 + c4];
            cpa16(&ASF(s, row, c4), sp, ok);
        }
#pragma unroll
        for (int it = 0; it < 2; ++it) {
            int idx = t + it * 256;
            int row = idx >> 4, c4 = (idx & 15) << 2;
            cpa16(&BSF(s, row, c4), &B[(size_t)(kt * 32 + row) * NC + bn0 + c4], true);
        }
    };

    load_tile(0, 0);
    CP_COMMIT();

    for (int kt = 0; kt < KT; ++kt) {
        int cb = kt & 1;
        if (kt + 1 < KT) load_tile(kt + 1, cb ^ 1);
        CP_COMMIT();
        CP_WAIT1();
        __syncthreads();

#pragma unroll
        for (int ks = 0; ks < 4; ++ks) {
            int kk = ks * 8;
            unsigned bf[4][2];
#pragma unroll
            for (int j = 0; j < 4; ++j) {
                bf[j][0] = bits(BSF(cb, kk + q,     wn + j * 8 + g));
                bf[j][1] = bits(BSF(cb, kk + q + 4, wn + j * 8 + g));
            }
#pragma unroll
            for (int i = 0; i < 2; ++i) {
                int r = wm + i * 16 + g;
                unsigned a0 = bits(ASF(cb, r,     kk + q));
                unsigned a1 = bits(ASF(cb, r + 8, kk + q));
                unsigned a2 = bits(ASF(cb, r,     kk + q + 4));
                unsigned a3 = bits(ASF(cb, r + 8, kk + q + 4));
#pragma unroll
                for (int j = 0; j < 4; ++j)
                    mma_tf32(acc[i][j][0], acc[i][j][1], acc[i][j][2], acc[i][j][3],
                             a0, a1, a2, a3, bf[j][0], bf[j][1]);
            }
        }
        __syncthreads();
    }

#pragma unroll
    for (int i = 0; i < 2; ++i) {
        int r0 = bm0 + wm + i * 16 + g;
#pragma unroll
        for (int j = 0; j < 4; ++j) {
            int c = bn0 + wn + j * 8 + q * 2;
            if (r0 < M)     *(float2*)&C[(size_t)r0 * NC + c]       = make_float2(acc[i][j][0], acc[i][j][1]);
            if (r0 + 8 < M) *(float2*)&C[(size_t)(r0 + 8) * NC + c] = make_float2(acc[i][j][2], acc[i][j][3]);
        }
    }
#undef ASF
#undef BSF
}

// ================= aggregation passes (width 64, warp per node) =================
// pass A: T1[d] = dd*(dd*C1[d] + sum_s ds*C1[s]);  u[d] = dd*(dd + sum_s ds)
__global__ void __launch_bounds__(256) k_aggA()
{
    int gt = blockIdx.x * 256 + threadIdx.x;
    int d = gt >> 5, lane = gt & 31;
    if (d >= NN) return;
    float dd = g_dis[d];
    float2 sv = *(const float2*)&g_C1[(size_t)d * 64 + lane * 2];
    float2 acc = make_float2(sv.x * dd, sv.y * dd);
    float sds = dd;                           // self contributes dd
    int e = g_ptr[d], e1 = g_ptr[d + 1];
    for (; e + 3 < e1; e += 4) {
        int n[4]; float ds[4]; float2 v[4];
#pragma unroll
        for (int u = 0; u < 4; ++u) { n[u] = g_csr[e + u]; ds[u] = g_dis[n[u]]; }
#pragma unroll
        for (int u = 0; u < 4; ++u) v[u] = *(const float2*)&g_C1[(size_t)n[u] * 64 + lane * 2];
#pragma unroll
        for (int u = 0; u < 4; ++u) {
            acc.x += v[u].x * ds[u]; acc.y += v[u].y * ds[u];
            sds += ds[u];
        }
    }
    for (; e < e1; ++e) {
        int n0 = g_csr[e];
        float ds0 = g_dis[n0];
        float2 v = *(const float2*)&g_C1[(size_t)n0 * 64 + lane * 2];
        acc.x += v.x * ds0; acc.y += v.y * ds0;
        sds += ds0;
    }
    *(float2*)&g_T1[(size_t)d * 64 + lane * 2] = make_float2(acc.x * dd, acc.y * dd);
    if (lane == 0) g_u[d] = dd * sds;
}
// pass B: Z[d] = dd*(dd*T1[d] + sum_s ds*T1[s]) + u[d]*c + b2
__global__ void __launch_bounds__(256) k_aggB(const float* __restrict__ b2)
{
    int gt = blockIdx.x * 256 + threadIdx.x;
    int d = gt >> 5, lane = gt & 31;
    if (d >= NN) return;
    float dd = g_dis[d];
    float2 sv = *(const float2*)&g_T1[(size_t)d * 64 + lane * 2];
    float2 acc = make_float2(sv.x * dd, sv.y * dd);
    int e = g_ptr[d], e1 = g_ptr[d + 1];
    for (; e + 3 < e1; e += 4) {
        int n[4]; float ds[4]; float2 v[4];
#pragma unroll
        for (int u = 0; u < 4; ++u) { n[u] = g_csr[e + u]; ds[u] = g_dis[n[u]]; }
#pragma unroll
        for (int u = 0; u < 4; ++u) v[u] = *(const float2*)&g_T1[(size_t)n[u] * 64 + lane * 2];
#pragma unroll
        for (int u = 0; u < 4; ++u) { acc.x += v[u].x * ds[u]; acc.y += v[u].y * ds[u]; }
    }
    for (; e < e1; ++e) {
        int n0 = g_csr[e];
        float ds0 = g_dis[n0];
        float2 v = *(const float2*)&g_T1[(size_t)n0 * 64 + lane * 2];
        acc.x += v.x * ds0; acc.y += v.y * ds0;
    }
    float uu = g_u[d];
    float2 cc = *(const float2*)&g_c[lane * 2];
    float2 bb = *(const float2*)&b2[lane * 2];
    *(float2*)&g_Z[(size_t)d * 64 + lane * 2] =
        make_float2(acc.x * dd + uu * cc.x + bb.x, acc.y * dd + uu * cc.y + bb.y);
}

// ================= decoder: Y = sigmoid(Z Z^T), 512 thr, 16 warps =================
#define DEC_SMEM (128*68*4 + 64*136*4)   // 69632 B; T[128][132] aliases it
#define TS 132
__global__ void __launch_bounds__(512) k_decode(float* __restrict__ Y, int M)
{
    int k = blockIdx.x;
    int bi = (int)((2.0f * NB + 1.0f - sqrtf((2.0f * NB + 1.0f) * (2.0f * NB + 1.0f) - 8.0f * k)) * 0.5f);
    if (bi < 0) bi = 0;
    while (bi * NB - bi * (bi - 1) / 2 > k) --bi;
    while ((bi + 1) * NB - (bi + 1) * bi / 2 <= k) ++bi;
    int bj = bi + (k - (bi * NB - bi * (bi - 1) / 2));

    extern __shared__ unsigned char sraw[];
    unsigned (*As)[68]  = (unsigned(*)[68])sraw;
    unsigned (*Bs)[136] = (unsigned(*)[136])(sraw + 128*68*4);
    float* T = (float*)sraw;

    int t = threadIdx.x, lane = t & 31, wid = t >> 5;
    int wm = (wid & 3) * 32, wn = (wid >> 2) * 32;
    int g = lane >> 2, q = lane & 3;
    int r0b = bi * 128, c0b = bj * 128;

#pragma unroll
    for (int it = 0; it < 4; ++it) {
        int idx = t + it * 512;
        int row = idx >> 4, c4 = (idx & 15) << 2;
        uint4 v = make_uint4(0u, 0u, 0u, 0u);
        if (r0b + row < M) v = *(const uint4*)&g_Z[(r0b + row) * 64 + c4];
        *(uint4*)&As[row][c4] = v;
    }
#pragma unroll
    for (int it = 0; it < 4; ++it) {
        int idx = t + it * 512;
        int col = idx & 127, c4 = (idx >> 7) << 2;
        uint4 v = make_uint4(0u, 0u, 0u, 0u);
        if (c0b + col < M) v = *(const uint4*)&g_Z[(c0b + col) * 64 + c4];
        Bs[c4 + 0][col] = v.x; Bs[c4 + 1][col] = v.y;
        Bs[c4 + 2][col] = v.z; Bs[c4 + 3][col] = v.w;
    }
    __syncthreads();

    float acc[2][4][4];
#pragma unroll
    for (int i = 0; i < 2; ++i)
#pragma unroll
        for (int j = 0; j < 4; ++j)
#pragma unroll
            for (int x = 0; x < 4; ++x) acc[i][j][x] = 0.f;

#pragma unroll
    for (int ks = 0; ks < 8; ++ks) {
        int kk = ks * 8;
        unsigned bf[4][2];
#pragma unroll
        for (int j = 0; j < 4; ++j) {
            bf[j][0] = Bs[kk + q][wn + j * 8 + g];
            bf[j][1] = Bs[kk + q + 4][wn + j * 8 + g];
        }
#pragma unroll
        for (int i = 0; i < 2; ++i) {
            int r = wm + i * 16 + g;
            unsigned a0 = As[r][kk + q],     a1 = As[r + 8][kk + q];
            unsigned a2 = As[r][kk + q + 4], a3 = As[r + 8][kk + q + 4];
#pragma unroll
            for (int j = 0; j < 4; ++j)
                mma_tf32(acc[i][j][0], acc[i][j][1], acc[i][j][2], acc[i][j][3],
                         a0, a1, a2, a3, bf[j][0], bf[j][1]);
        }
    }

#pragma unroll
    for (int i = 0; i < 2; ++i)
#pragma unroll
        for (int j = 0; j < 4; ++j)
#pragma unroll
            for (int x = 0; x < 4; ++x)
                acc[i][j][x] = fsig(acc[i][j][x]);

    // normal half: direct float2 stores
#pragma unroll
    for (int i = 0; i < 2; ++i) {
        int r = r0b + wm + i * 16 + g;
#pragma unroll
        for (int j = 0; j < 4; ++j) {
            int c = c0b + wn + j * 8 + q * 2;
            if (c < M) {
                if (r < M)     *(float2*)&Y[(size_t)r * M + c]       = make_float2(acc[i][j][0], acc[i][j][1]);
                if (r + 8 < M) *(float2*)&Y[(size_t)(r + 8) * M + c] = make_float2(acc[i][j][2], acc[i][j][3]);
            }
        }
    }

    // mirror half via smem transpose -> STG.128 rows
    if (bi != bj) {
        __syncthreads();
#pragma unroll
        for (int i = 0; i < 2; ++i) {
#pragma unroll
            for (int j = 0; j < 4; ++j) {
                int cc = wn + j * 8 + q * 2;
                int rr = wm + i * 16 + g;
                T[cc * TS + rr]           = acc[i][j][0];
                T[(cc + 1) * TS + rr]     = acc[i][j][1];
                T[cc * TS + rr + 8]       = acc[i][j][2];
                T[(cc + 1) * TS + rr + 8] = acc[i][j][3];
            }
        }
        __syncthreads();
#pragma unroll
        for (int it = 0; it < 8; ++it) {
            int idx = t + it * 512;
            int cc = idx >> 5, rc = (idx & 31) << 2;
            int crow = c0b + cc;
            if (crow < M) {
                float4 v = *(const float4*)&T[cc * TS + rc];
                if (r0b + rc + 3 < M) {
                    *(float4*)&Y[(size_t)crow * M + r0b + rc] = v;
                } else {
                    float vv[4] = {v.x, v.y, v.z, v.w};
                    for (int j = 0; j < 4; ++j)
                        if (r0b + rc + j < M) Y[(size_t)crow * M + r0b + rc + j] = vv[j];
                }
            }
        }
    }
}

// ================= launch =================
extern "C" void kernel_launch(void* const* d_in, const int* in_sizes, int n_in,
                              void* d_out, int out_size)
{
    const float* X  = (const float*)d_in[0];
    const int*   ei = (const int*)  d_in[1];
    const float* W1 = (const float*)d_in[2];
    const float* b1 = (const float*)d_in[3];
    const float* W2 = (const float*)d_in[4];
    const float* b2 = (const float*)d_in[5];
    float* Y = (float*)d_out;

    int E = in_sizes[1] / 2;
    if (E > NE) E = NE;
    const int* src = ei;
    const int* dst = ei + E;

    static bool init_done = false;
    static cudaStream_t s2;
    static cudaEvent_t evA, evB;
    static void *p_cnt, *p_w12, *p_c1;
    if (!init_done) {
        cudaFuncSetAttribute(k_decode, cudaFuncAttributeMaxDynamicSharedMemorySize, DEC_SMEM);
        cudaFuncSetAttribute(k_gemm<F0, F2>, cudaFuncAttributeMaxDynamicSharedMemorySize, GEMM_SMEM);
        cudaStreamCreateWithFlags(&s2, cudaStreamNonBlocking);
        cudaEventCreateWithFlags(&evA, cudaEventDisableTiming);
        cudaEventCreateWithFlags(&evB, cudaEventDisableTiming);
        cudaGetSymbolAddress(&p_cnt, g_cnt);
        cudaGetSymbolAddress(&p_w12, g_W12);
        cudaGetSymbolAddress(&p_c1, g_C1);
        init_done = true;
    }

    // fork: W12 + X@W12 on s2 (needs only X, W1, W2, b1); CSR build on stream 0
    cudaEventRecord(evA, 0);
    cudaStreamWaitEvent(s2, evA, 0);

    k_w12<<<F0 + 1, 64, 0, s2>>>(W1, W2, b1);
    dim3 g1(1, (NN + 127) / 128);
    k_gemm<F0, F2><<<g1, 256, GEMM_SMEM, s2>>>(X, (const float*)p_w12, (float*)p_c1, NN);
    cudaEventRecord(evB, s2);

    cudaMemsetAsync(p_cnt, 0, NN * sizeof(int), 0);
    k_count  <<<(E + 255) / 256, 256>>>(dst, E);
    k_scan   <<<1, 1024>>>();
    k_scatter<<<(E + 255) / 256, 256>>>(src, dst, E);

    // join: aggA needs C1 (s2) + CSR/dis (stream 0)
    cudaStreamWaitEvent(0, evB, 0);

    k_aggA<<<(NN * 32 + 255) / 256, 256>>>();
    k_aggB<<<(NN * 32 + 255) / 256, 256>>>(b2);

    k_decode<<<NB * (NB + 1) / 2, 512, DEC_SMEM>>>(Y, NN);
}

// round 10
// speedup vs baseline: 1.3490x; 1.0096x over previous
#include <cuda_runtime.h>
#include <math.h>

#define NN 10000
#define NE 320000
#define F0 512
#define F2 64
#define NB 79            // ceil(10000/128)

// ---- scratch (no cudaMalloc allowed) ----
__device__ int   g_cnt[NN];
__device__ int   g_ptr[NN + 1];
__device__ int   g_cur[NN];
__device__ int   g_csr[NE];
__device__ float g_dis[NN];
__device__ float g_u[NN];                         // (L·1)[d]
__device__ __align__(16) float g_W12[F0 * F2];    // W1 @ W2 (fp32)
__device__ __align__(16) float g_c[F2];           // b1^T W2
__device__ __align__(16) float g_C1[NN * F2];     // X @ W12
__device__ __align__(16) float g_T1[NN * F2];     // L @ C1
__device__ __align__(16) float g_Z [NN * F2];     // L @ T1 + u c^T + b2

// ---- tf32 (raw-bit) / cp.async helpers ----
__device__ __forceinline__ unsigned bits(float f) { return __float_as_uint(f); }
__device__ __forceinline__ void mma_tf32(float& d0, float& d1, float& d2, float& d3,
                                         unsigned a0, unsigned a1, unsigned a2, unsigned a3,
                                         unsigned b0, unsigned b1) {
    asm volatile("mma.sync.aligned.m16n8k8.row.col.f32.tf32.tf32.f32 "
                 "{%0,%1,%2,%3}, {%4,%5,%6,%7}, {%8,%9}, {%0,%1,%2,%3};"
                 : "+f"(d0), "+f"(d1), "+f"(d2), "+f"(d3)
                 : "r"(a0), "r"(a1), "r"(a2), "r"(a3), "r"(b0), "r"(b1));
}
__device__ __forceinline__ void cpa16(float* dst_smem, const float* src, bool pred) {
    unsigned sa = (unsigned)__cvta_generic_to_shared(dst_smem);
    int sz = pred ? 16 : 0;
    asm volatile("cp.async.cg.shared.global [%0], [%1], 16, %2;" :: "r"(sa), "l"(src), "r"(sz));
}
#define CP_COMMIT() asm volatile("cp.async.commit_group;")
#define CP_WAIT1()  asm volatile("cp.async.wait_group 1;")

// sigmoid(x) = 0.5*tanh(x/2) + 0.5 : single MUFU op (tanh.approx, sm_75+)
__device__ __forceinline__ float fsig(float x) {
    float th;
    asm("tanh.approx.f32 %0, %1;" : "=f"(th) : "f"(x * 0.5f));
    return fmaf(th, 0.5f, 0.5f);
}

// ================= CSR build =================
__global__ void k_count(const int* __restrict__ dst, int E) {
    int i = blockIdx.x * 256 + threadIdx.x;
    if (i < E) atomicAdd(&g_cnt[dst[i]], 1);
}
// single block; thread t owns elements [t*10, t*10+10). 3 syncs total.
__global__ void __launch_bounds__(1024) k_scan() {
    __shared__ int wsum[32];
    int t = threadIdx.x, lane = t & 31, w = t >> 5;
    int base = t * 10;
    int v[10];
#pragma unroll
    for (int i = 0; i < 10; ++i)
        v[i] = (base + i < NN) ? g_cnt[base + i] : 0;
    int tot = 0;
#pragma unroll
    for (int i = 0; i < 10; ++i) tot += v[i];
    // warp inclusive scan of per-thread totals
    int s = tot;
#pragma unroll
    for (int off = 1; off < 32; off <<= 1) {
        int x = __shfl_up_sync(0xFFFFFFFFu, s, off);
        if (lane >= off) s += x;
    }
    if (lane == 31) wsum[w] = s;
    __syncthreads();
    if (w == 0) {
        int y = wsum[lane];
#pragma unroll
        for (int off = 1; off < 32; off <<= 1) {
            int x = __shfl_up_sync(0xFFFFFFFFu, y, off);
            if (lane >= off) y += x;
        }
        wsum[lane] = y;
    }
    __syncthreads();
    int run = s - tot + (w > 0 ? wsum[w - 1] : 0);   // exclusive prefix for this thread
#pragma unroll
    for (int i = 0; i < 10; ++i) {
        int idx = base + i;
        if (idx < NN) {
            g_ptr[idx] = run;
            g_cur[idx] = run;
            g_dis[idx] = rsqrtf((float)(v[i] + 1));
            run += v[i];
        }
    }
    if (t == 0) g_ptr[NN] = wsum[31];
}
__global__ void k_scatter(const int* __restrict__ src, const int* __restrict__ dst, int E) {
    int i = blockIdx.x * 256 + threadIdx.x;
    if (i < E) {
        int pos = atomicAdd(&g_cur[dst[i]], 1);
        g_csr[pos] = src[i];
    }
}

// ================= W12 = W1 @ W2 (fp32), c = b1^T W2 =================
__global__ void __launch_bounds__(64) k_w12(const float* __restrict__ W1,
                                            const float* __restrict__ W2,
                                            const float* __restrict__ b1)
{
    int n = threadIdx.x;
    int k = blockIdx.x;
    const float* a = (k < F0) ? &W1[k * 256] : b1;
    float acc = 0.f;
#pragma unroll 4
    for (int j = 0; j < 256; ++j) acc = fmaf(a[j], W2[j * F2 + n], acc);
    if (k < F0) g_W12[k * F2 + n] = acc;
    else        g_c[n] = acc;
}

// ================= tf32 GEMM: C = A @ B.  BM=128, BN=64, BK=32 =================
#define GEMM_SMEM ((2*128*36 + 2*32*72) * 4)
template<int K, int NC>
__global__ void __launch_bounds__(256) k_gemm(const float* __restrict__ A,
                                              const float* __restrict__ B,
                                              float* __restrict__ C, int M)
{
    extern __shared__ float gsm[];
    float* Asm = gsm;                    // [2][128][36]
    float* Bsm = gsm + 2 * 128 * 36;     // [2][32][72]
#define ASF(s, r, c) Asm[(s) * (128 * 36) + (r) * 36 + (c)]
#define BSF(s, r, c) Bsm[(s) * (32 * 72) + (r) * 72 + (c)]

    int t = threadIdx.x, lane = t & 31, wid = t >> 5;
    int wm = (wid & 3) * 32, wn = (wid >> 2) * 32;
    int g = lane >> 2, q = lane & 3;
    int bm0 = blockIdx.y * 128, bn0 = blockIdx.x * 64;

    float acc[2][4][4];
#pragma unroll
    for (int i = 0; i < 2; ++i)
#pragma unroll
        for (int j = 0; j < 4; ++j)
#pragma unroll
            for (int x = 0; x < 4; ++x) acc[i][j][x] = 0.f;

    const int KT = K / 32;

    auto load_tile = [&](int kt, int s) {
#pragma unroll
        for (int it = 0; it < 4; ++it) {
            int idx = t + it * 256;
            int row = idx >> 3, c4 = (idx & 7) << 2;
            int rg = bm0 + row;
            bool ok = rg < M;
            const float* sp = &A[(size_t)(ok ? rg : 0) * K + kt * 32 + c4];
            cpa16(&ASF(s, row, c4), sp, ok);
        }
#pragma unroll
        for (int it = 0; it < 2; ++it) {
            int idx = t + it * 256;
            int row = idx >> 4, c4 = (idx & 15) << 2;
            cpa16(&BSF(s, row, c4), &B[(size_t)(kt * 32 + row) * NC + bn0 + c4], true);
        }
    };

    load_tile(0, 0);
    CP_COMMIT();

    for (int kt = 0; kt < KT; ++kt) {
        int cb = kt & 1;
        if (kt + 1 < KT) load_tile(kt + 1, cb ^ 1);
        CP_COMMIT();
        CP_WAIT1();
        __syncthreads();

#pragma unroll
        for (int ks = 0; ks < 4; ++ks) {
            int kk = ks * 8;
            unsigned bf[4][2];
#pragma unroll
            for (int j = 0; j < 4; ++j) {
                bf[j][0] = bits(BSF(cb, kk + q,     wn + j * 8 + g));
                bf[j][1] = bits(BSF(cb, kk + q + 4, wn + j * 8 + g));
            }
#pragma unroll
            for (int i = 0; i < 2; ++i) {
                int r = wm + i * 16 + g;
                unsigned a0 = bits(ASF(cb, r,     kk + q));
                unsigned a1 = bits(ASF(cb, r + 8, kk + q));
                unsigned a2 = bits(ASF(cb, r,     kk + q + 4));
                unsigned a3 = bits(ASF(cb, r + 8, kk + q + 4));
#pragma unroll
                for (int j = 0; j < 4; ++j)
                    mma_tf32(acc[i][j][0], acc[i][j][1], acc[i][j][2], acc[i][j][3],
                             a0, a1, a2, a3, bf[j][0], bf[j][1]);
            }
        }
        __syncthreads();
    }

#pragma unroll
    for (int i = 0; i < 2; ++i) {
        int r0 = bm0 + wm + i * 16 + g;
#pragma unroll
        for (int j = 0; j < 4; ++j) {
            int c = bn0 + wn + j * 8 + q * 2;
            if (r0 < M)     *(float2*)&C[(size_t)r0 * NC + c]       = make_float2(acc[i][j][0], acc[i][j][1]);
            if (r0 + 8 < M) *(float2*)&C[(size_t)(r0 + 8) * NC + c] = make_float2(acc[i][j][2], acc[i][j][3]);
        }
    }
#undef ASF
#undef BSF
}

// ================= aggregation passes (width 64, warp per node) =================
__global__ void __launch_bounds__(256) k_aggA()
{
    int gt = blockIdx.x * 256 + threadIdx.x;
    int d = gt >> 5, lane = gt & 31;
    if (d >= NN) return;
    float dd = g_dis[d];
    float2 sv = *(const float2*)&g_C1[(size_t)d * 64 + lane * 2];
    float2 acc = make_float2(sv.x * dd, sv.y * dd);
    float sds = dd;
    int e = g_ptr[d], e1 = g_ptr[d + 1];
    for (; e + 3 < e1; e += 4) {
        int n[4]; float ds[4]; float2 v[4];
#pragma unroll
        for (int u = 0; u < 4; ++u) { n[u] = g_csr[e + u]; ds[u] = g_dis[n[u]]; }
#pragma unroll
        for (int u = 0; u < 4; ++u) v[u] = *(const float2*)&g_C1[(size_t)n[u] * 64 + lane * 2];
#pragma unroll
        for (int u = 0; u < 4; ++u) {
            acc.x += v[u].x * ds[u]; acc.y += v[u].y * ds[u];
            sds += ds[u];
        }
    }
    for (; e < e1; ++e) {
        int n0 = g_csr[e];
        float ds0 = g_dis[n0];
        float2 v = *(const float2*)&g_C1[(size_t)n0 * 64 + lane * 2];
        acc.x += v.x * ds0; acc.y += v.y * ds0;
        sds += ds0;
    }
    *(float2*)&g_T1[(size_t)d * 64 + lane * 2] = make_float2(acc.x * dd, acc.y * dd);
    if (lane == 0) g_u[d] = dd * sds;
}
__global__ void __launch_bounds__(256) k_aggB(const float* __restrict__ b2)
{
    int gt = blockIdx.x * 256 + threadIdx.x;
    int d = gt >> 5, lane = gt & 31;
    if (d >= NN) return;
    float dd = g_dis[d];
    float2 sv = *(const float2*)&g_T1[(size_t)d * 64 + lane * 2];
    float2 acc = make_float2(sv.x * dd, sv.y * dd);
    int e = g_ptr[d], e1 = g_ptr[d + 1];
    for (; e + 3 < e1; e += 4) {
        int n[4]; float ds[4]; float2 v[4];
#pragma unroll
        for (int u = 0; u < 4; ++u) { n[u] = g_csr[e + u]; ds[u] = g_dis[n[u]]; }
#pragma unroll
        for (int u = 0; u < 4; ++u) v[u] = *(const float2*)&g_T1[(size_t)n[u] * 64 + lane * 2];
#pragma unroll
        for (int u = 0; u < 4; ++u) { acc.x += v[u].x * ds[u]; acc.y += v[u].y * ds[u]; }
    }
    for (; e < e1; ++e) {
        int n0 = g_csr[e];
        float ds0 = g_dis[n0];
        float2 v = *(const float2*)&g_T1[(size_t)n0 * 64 + lane * 2];
        acc.x += v.x * ds0; acc.y += v.y * ds0;
    }
    float uu = g_u[d];
    float2 cc = *(const float2*)&g_c[lane * 2];
    float2 bb = *(const float2*)&b2[lane * 2];
    *(float2*)&g_Z[(size_t)d * 64 + lane * 2] =
        make_float2(acc.x * dd + uu * cc.x + bb.x, acc.y * dd + uu * cc.y + bb.y);
}

// ================= decoder: Y = sigmoid(Z Z^T), 512 thr, 16 warps =================
#define DEC_SMEM (128*68*4 + 64*136*4)   // 69632 B; T[128][132] aliases it
#define TS 132
__global__ void __launch_bounds__(512) k_decode(float* __restrict__ Y, int M)
{
    int k = blockIdx.x;
    int bi = (int)((2.0f * NB + 1.0f - sqrtf((2.0f * NB + 1.0f) * (2.0f * NB + 1.0f) - 8.0f * k)) * 0.5f);
    if (bi < 0) bi = 0;
    while (bi * NB - bi * (bi - 1) / 2 > k) --bi;
    while ((bi + 1) * NB - (bi + 1) * bi / 2 <= k) ++bi;
    int bj = bi + (k - (bi * NB - bi * (bi - 1) / 2));

    extern __shared__ unsigned char sraw[];
    unsigned (*As)[68]  = (unsigned(*)[68])sraw;
    unsigned (*Bs)[136] = (unsigned(*)[136])(sraw + 128*68*4);
    float* T = (float*)sraw;

    int t = threadIdx.x, lane = t & 31, wid = t >> 5;
    int wm = (wid & 3) * 32, wn = (wid >> 2) * 32;
    int g = lane >> 2, q = lane & 3;
    int r0b = bi * 128, c0b = bj * 128;

#pragma unroll
    for (int it = 0; it < 4; ++it) {
        int idx = t + it * 512;
        int row = idx >> 4, c4 = (idx & 15) << 2;
        uint4 v = make_uint4(0u, 0u, 0u, 0u);
        if (r0b + row < M) v = *(const uint4*)&g_Z[(r0b + row) * 64 + c4];
        *(uint4*)&As[row][c4] = v;
    }
#pragma unroll
    for (int it = 0; it < 4; ++it) {
        int idx = t + it * 512;
        int col = idx & 127, c4 = (idx >> 7) << 2;
        uint4 v = make_uint4(0u, 0u, 0u, 0u);
        if (c0b + col < M) v = *(const uint4*)&g_Z[(c0b + col) * 64 + c4];
        Bs[c4 + 0][col] = v.x; Bs[c4 + 1][col] = v.y;
        Bs[c4 + 2][col] = v.z; Bs[c4 + 3][col] = v.w;
    }
    __syncthreads();

    float acc[2][4][4];
#pragma unroll
    for (int i = 0; i < 2; ++i)
#pragma unroll
        for (int j = 0; j < 4; ++j)
#pragma unroll
            for (int x = 0; x < 4; ++x) acc[i][j][x] = 0.f;

#pragma unroll
    for (int ks = 0; ks < 8; ++ks) {
        int kk = ks * 8;
        unsigned bf[4][2];
#pragma unroll
        for (int j = 0; j < 4; ++j) {
            bf[j][0] = Bs[kk + q][wn + j * 8 + g];
            bf[j][1] = Bs[kk + q + 4][wn + j * 8 + g];
        }
#pragma unroll
        for (int i = 0; i < 2; ++i) {
            int r = wm + i * 16 + g;
            unsigned a0 = As[r][kk + q],     a1 = As[r + 8][kk + q];
            unsigned a2 = As[r][kk + q + 4], a3 = As[r + 8][kk + q + 4];
#pragma unroll
            for (int j = 0; j < 4; ++j)
                mma_tf32(acc[i][j][0], acc[i][j][1], acc[i][j][2], acc[i][j][3],
                         a0, a1, a2, a3, bf[j][0], bf[j][1]);
        }
    }

#pragma unroll
    for (int i = 0; i < 2; ++i)
#pragma unroll
        for (int j = 0; j < 4; ++j)
#pragma unroll
            for (int x = 0; x < 4; ++x)
                acc[i][j][x] = fsig(acc[i][j][x]);

    // normal half: direct float2 stores
#pragma unroll
    for (int i = 0; i < 2; ++i) {
        int r = r0b + wm + i * 16 + g;
#pragma unroll
        for (int j = 0; j < 4; ++j) {
            int c = c0b + wn + j * 8 + q * 2;
            if (c < M) {
                if (r < M)     *(float2*)&Y[(size_t)r * M + c]       = make_float2(acc[i][j][0], acc[i][j][1]);
                if (r + 8 < M) *(float2*)&Y[(size_t)(r + 8) * M + c] = make_float2(acc[i][j][2], acc[i][j][3]);
            }
        }
    }

    // mirror half via smem transpose -> STG.128 rows
    if (bi != bj) {
        __syncthreads();
#pragma unroll
        for (int i = 0; i < 2; ++i) {
#pragma unroll
            for (int j = 0; j < 4; ++j) {
                int cc = wn + j * 8 + q * 2;
                int rr = wm + i * 16 + g;
                T[cc * TS + rr]           = acc[i][j][0];
                T[(cc + 1) * TS + rr]     = acc[i][j][1];
                T[cc * TS + rr + 8]       = acc[i][j][2];
                T[(cc + 1) * TS + rr + 8] = acc[i][j][3];
            }
        }
        __syncthreads();
#pragma unroll
        for (int it = 0; it < 8; ++it) {
            int idx = t + it * 512;
            int cc = idx >> 5, rc = (idx & 31) << 2;
            int crow = c0b + cc;
            if (crow < M) {
                float4 v = *(const float4*)&T[cc * TS + rc];
                if (r0b + rc + 3 < M) {
                    *(float4*)&Y[(size_t)crow * M + r0b + rc] = v;
                } else {
                    float vv[4] = {v.x, v.y, v.z, v.w};
                    for (int j = 0; j < 4; ++j)
                        if (r0b + rc + j < M) Y[(size_t)crow * M + r0b + rc + j] = vv[j];
                }
            }
        }
    }
}

// ================= launch =================
extern "C" void kernel_launch(void* const* d_in, const int* in_sizes, int n_in,
                              void* d_out, int out_size)
{
    const float* X  = (const float*)d_in[0];
    const int*   ei = (const int*)  d_in[1];
    const float* W1 = (const float*)d_in[2];
    const float* b1 = (const float*)d_in[3];
    const float* W2 = (const float*)d_in[4];
    const float* b2 = (const float*)d_in[5];
    float* Y = (float*)d_out;

    int E = in_sizes[1] / 2;
    if (E > NE) E = NE;
    const int* src = ei;
    const int* dst = ei + E;

    static bool init_done = false;
    static cudaStream_t s2;
    static cudaEvent_t evA, evB;
    static void *p_cnt, *p_w12, *p_c1;
    if (!init_done) {
        cudaFuncSetAttribute(k_decode, cudaFuncAttributeMaxDynamicSharedMemorySize, DEC_SMEM);
        cudaFuncSetAttribute(k_gemm<F0, F2>, cudaFuncAttributeMaxDynamicSharedMemorySize, GEMM_SMEM);
        cudaStreamCreateWithFlags(&s2, cudaStreamNonBlocking);
        cudaEventCreateWithFlags(&evA, cudaEventDisableTiming);
        cudaEventCreateWithFlags(&evB, cudaEventDisableTiming);
        cudaGetSymbolAddress(&p_cnt, g_cnt);
        cudaGetSymbolAddress(&p_w12, g_W12);
        cudaGetSymbolAddress(&p_c1, g_C1);
        init_done = true;
    }

    // fork: W12 + X@W12 on s2; CSR build on stream 0
    cudaEventRecord(evA, 0);
    cudaStreamWaitEvent(s2, evA, 0);

    k_w12<<<F0 + 1, 64, 0, s2>>>(W1, W2, b1);
    dim3 g1(1, (NN + 127) / 128);
    k_gemm<F0, F2><<<g1, 256, GEMM_SMEM, s2>>>(X, (const float*)p_w12, (float*)p_c1, NN);
    cudaEventRecord(evB, s2);

    cudaMemsetAsync(p_cnt, 0, NN * sizeof(int), 0);
    k_count  <<<(E + 255) / 256, 256>>>(dst, E);
    k_scan   <<<1, 1024>>>();
    k_scatter<<<(E + 255) / 256, 256>>>(src, dst, E);

    // join: aggA needs C1 (s2) + CSR/dis (stream 0)
    cudaStreamWaitEvent(0, evB, 0);

    k_aggA<<<(NN * 32 + 255) / 256, 256>>>();
    k_aggB<<<(NN * 32 + 255) / 256, 256>>>(b2);

    k_decode<<<NB * (NB + 1) / 2, 512, DEC_SMEM>>>(Y, NN);
}